// round 1
// baseline (speedup 1.0000x reference)
#include <cuda_runtime.h>

#define HH 2048
#define WW 2048
#define TPB 256
#define ROWS 32          // output rows per block strip
#define TILE_C 256       // primary cols per block
#define SH_C (TILE_C + 2)

__device__ float g_acc[3];   // [0]=sum|fx/Ec|, [1]=sum|fy/Ec|, [2]=sum E

__global__ void zero_acc_kernel() {
    g_acc[0] = 0.f; g_acc[1] = 0.f; g_acc[2] = 0.f;
}

__global__ __launch_bounds__(TPB) void loss_main_kernel(
    const float* __restrict__ pred_E,
    const float* __restrict__ pred_v,
    const float* __restrict__ strain)
{
    __shared__ float sE[2][SH_C], sXX[2][SH_C], sYY[2][SH_C], sXY[2][SH_C];
    __shared__ float red[8][3];

    const int tid  = threadIdx.x;
    const int col0 = blockIdx.x * TILE_C;
    const int row0 = blockIdx.y * ROWS;
    const int j    = col0 + tid;                 // output column
    const bool out_col = (j < WW - 2);

    float accx = 0.f, accy = 0.f, accE = 0.f;

    // 3-row register ring (a = oldest of the 2 kept rows, b = previous row)
    float h3E_a = 0.f, h3E_b = 0.f;
    float h3XX_a = 0.f, h3XX_b = 0.f;
    float h3XY_a = 0.f, h3XY_b = 0.f;
    float yy0_a = 0.f, yy0_b = 0.f, yy2_a = 0.f, yy2_b = 0.f;
    float xy0_a = 0.f, xy0_b = 0.f, xy2_a = 0.f, xy2_b = 0.f;

    for (int k = 0; k < ROWS + 2; ++k) {
        const int r   = row0 + k;
        const int buf = k & 1;

        // ---- load + per-element stress into shared row buffer ----
        for (int c = tid; c < SH_C; c += TPB) {
            float E = 0.f, xx = 0.f, yy = 0.f, xy = 0.f;
            const int gc = col0 + c;
            if (r < HH && gc < WW) {
                const int idx = r * WW + gc;
                const float e   = pred_E[idx];
                const float v   = pred_v[idx];
                const float exx = strain[3 * idx + 0];
                const float eyy = strain[3 * idx + 1];
                const float exy = strain[3 * idx + 2];
                const float frac = e / (1.f - v * v);
                E  = e;
                xx = (exx + v * eyy) * frac;
                yy = (v * exx + eyy) * frac;
                xy = exy * (1.f - v) * 0.5f * frac;
                // ownership partition for sum(E): primary col, interior row of strip
                if (c < TILE_C && k < ROWS) accE += e;
            }
            sE [buf][c] = E;
            sXX[buf][c] = xx;
            sYY[buf][c] = yy;
            sXY[buf][c] = xy;
        }
        __syncthreads();

        // ---- gather this row's horizontal sums / column taps ----
        const float h3E  = sE [buf][tid] + sE [buf][tid + 1] + sE [buf][tid + 2];
        const float h3XX = sXX[buf][tid] + sXX[buf][tid + 1] + sXX[buf][tid + 2];
        const float xy0  = sXY[buf][tid];
        const float xy1  = sXY[buf][tid + 1];
        const float xy2  = sXY[buf][tid + 2];
        const float h3XY = xy0 + xy1 + xy2;
        const float yy0  = sYY[buf][tid];
        const float yy2  = sYY[buf][tid + 2];

        if (k >= 2) {
            const int i = r - 2;                 // output row
            if (out_col && i < HH - 2) {
                const float Econv = h3E_a + h3E_b + h3E;
                const float fx = (h3XX - h3XX_a) + (xy0_a + xy0_b + xy0)
                                                 - (xy2_a + xy2_b + xy2);
                const float fy = (yy0_a + yy0_b + yy0) - (yy2_a + yy2_b + yy2)
                                 + (h3XY - h3XY_a);
                const float inv = 1.f / Econv;   // E>0 => Econv>0
                accx += fabsf(fx * inv);
                accy += fabsf(fy * inv);
            }
        }
        // rotate ring
        h3E_a  = h3E_b;  h3E_b  = h3E;
        h3XX_a = h3XX_b; h3XX_b = h3XX;
        h3XY_a = h3XY_b; h3XY_b = h3XY;
        yy0_a  = yy0_b;  yy0_b  = yy0;
        yy2_a  = yy2_b;  yy2_b  = yy2;
        xy0_a  = xy0_b;  xy0_b  = xy0;
        xy2_a  = xy2_b;  xy2_b  = xy2;
    }

    // ---- block reduction ----
    const int lane = tid & 31;
    const int warp = tid >> 5;
    #pragma unroll
    for (int o = 16; o > 0; o >>= 1) {
        accx += __shfl_down_sync(0xFFFFFFFFu, accx, o);
        accy += __shfl_down_sync(0xFFFFFFFFu, accy, o);
        accE += __shfl_down_sync(0xFFFFFFFFu, accE, o);
    }
    if (lane == 0) {
        red[warp][0] = accx; red[warp][1] = accy; red[warp][2] = accE;
    }
    __syncthreads();
    if (warp == 0) {
        float ax = (lane < 8) ? red[lane][0] : 0.f;
        float ay = (lane < 8) ? red[lane][1] : 0.f;
        float aE = (lane < 8) ? red[lane][2] : 0.f;
        #pragma unroll
        for (int o = 4; o > 0; o >>= 1) {
            ax += __shfl_down_sync(0xFFFFFFFFu, ax, o);
            ay += __shfl_down_sync(0xFFFFFFFFu, ay, o);
            aE += __shfl_down_sync(0xFFFFFFFFu, aE, o);
        }
        if (lane == 0) {
            atomicAdd(&g_acc[0], ax);
            atomicAdd(&g_acc[1], ay);
            atomicAdd(&g_acc[2], aE);
        }
    }
}

__global__ void finalize_kernel(float* __restrict__ out) {
    const float invM = 1.0f / ((float)(WW - 2) * (float)(HH - 2));
    const float invN = 1.0f / ((float)WW * (float)HH);
    out[0] = g_acc[0] * invM + g_acc[1] * invM
           + fabsf(g_acc[2] * invN - 1.0f) * 0.01f;
}

extern "C" void kernel_launch(void* const* d_in, const int* in_sizes, int n_in,
                              void* d_out, int out_size) {
    const float* pred_E = (const float*)d_in[0];
    const float* pred_v = (const float*)d_in[1];
    const float* strain = (const float*)d_in[2];

    zero_acc_kernel<<<1, 1>>>();
    dim3 grid(WW / TILE_C, HH / ROWS);   // 8 x 64 = 512 blocks
    loss_main_kernel<<<grid, TPB>>>(pred_E, pred_v, strain);
    finalize_kernel<<<1, 1>>>((float*)d_out);
}

// round 2
// speedup vs baseline: 1.5773x; 1.5773x over previous
#include <cuda_runtime.h>

#define HH 2048
#define WW 2048
#define TPB 256
#define WARPS (TPB / 32)
#define CPW 30                         // output columns per warp
#define CPB (WARPS * CPW)              // 240 output columns per block
#define ROWS 32                        // output rows per strip
#define GRID_X ((WW - 2 + CPB - 1) / CPB)   // 9
#define GRID_Y (HH / ROWS)                  // 64
#define NBLOCKS (GRID_X * GRID_Y)           // 576

__device__ float g_acc[3];       // zero-initialized at module load; reset by last block
__device__ unsigned g_count;

__global__ __launch_bounds__(TPB) void loss_fused_kernel(
    const float* __restrict__ pred_E,
    const float* __restrict__ pred_v,
    const float* __restrict__ strain,
    float* __restrict__ out)
{
    const int tid  = threadIdx.x;
    const int lane = tid & 31;
    const int warp = tid >> 5;
    const int col  = (blockIdx.x * WARPS + warp) * CPW + lane;  // input column
    const int row0 = blockIdx.y * ROWS;
    const bool col_ok  = (col < WW);
    const bool own_col = (lane < CPW) && col_ok;      // unique owner of this column (for sum E)
    const bool out_col = (lane < CPW) && (col < WW - 2);

    float accx = 0.f, accy = 0.f, accE = 0.f;

    // register ring: rows i (a) and i+1 (b) of the running vertical sums
    float h3E_a = 0.f, h3E_b = 0.f;
    float h3XX_a = 0.f, h3XX_b = 0.f;
    float h3XY_a = 0.f, h3XY_b = 0.f;
    float yy0_a = 0.f, yy0_b = 0.f, yy2_a = 0.f, yy2_b = 0.f;
    float xy0_a = 0.f, xy0_b = 0.f, xy2_a = 0.f, xy2_b = 0.f;

    // raw prefetch registers
    float cE, cV, cXX, cYY, cXY;     // current row raw inputs
    {
        const bool ok = col_ok;      // row0 < HH always
        const int idx = row0 * WW + col;
        cE  = ok ? pred_E[idx] : 0.f;
        cV  = ok ? pred_v[idx] : 0.f;
        cXX = ok ? strain[3 * idx + 0] : 0.f;
        cYY = ok ? strain[3 * idx + 1] : 0.f;
        cXY = ok ? strain[3 * idx + 2] : 0.f;
    }

    #pragma unroll 2
    for (int k = 0; k < ROWS + 2; ++k) {
        const int r = row0 + k;

        // ---- prefetch raw row r+1 ----
        float nE = 0.f, nV = 0.f, nXX = 0.f, nYY = 0.f, nXY = 0.f;
        if (k < ROWS + 1) {
            const bool ok = (r + 1 < HH) && col_ok;
            const int idx = (r + 1) * WW + col;
            if (ok) {
                nE  = pred_E[idx];
                nV  = pred_v[idx];
                nXX = strain[3 * idx + 0];
                nYY = strain[3 * idx + 1];
                nXY = strain[3 * idx + 2];
            }
        }

        // ---- stress for current row ----
        const float frac = __fdividef(cE, 1.f - cV * cV);
        const float sxx = (cXX + cV * cYY) * frac;
        const float syy = (cV * cXX + cYY) * frac;
        const float sxy = cXY * (1.f - cV) * 0.5f * frac;

        if (own_col && k < ROWS) accE += cE;

        // ---- horizontal gathers via shuffle ----
        const float E1  = __shfl_down_sync(0xFFFFFFFFu, cE,  1);
        const float E2  = __shfl_down_sync(0xFFFFFFFFu, cE,  2);
        const float XX1 = __shfl_down_sync(0xFFFFFFFFu, sxx, 1);
        const float XX2 = __shfl_down_sync(0xFFFFFFFFu, sxx, 2);
        const float XY1 = __shfl_down_sync(0xFFFFFFFFu, sxy, 1);
        const float XY2 = __shfl_down_sync(0xFFFFFFFFu, sxy, 2);
        const float YY2 = __shfl_down_sync(0xFFFFFFFFu, syy, 2);

        const float h3E  = cE  + E1  + E2;
        const float h3XX = sxx + XX1 + XX2;
        const float h3XY = sxy + XY1 + XY2;

        if (k >= 2) {
            const int i = r - 2;                       // output row
            if (out_col && i < HH - 2) {
                const float Econv = h3E_a + h3E_b + h3E;
                const float fx = (h3XX - h3XX_a)
                               + (xy0_a + xy0_b + sxy) - (xy2_a + xy2_b + XY2);
                const float fy = (yy0_a + yy0_b + syy) - (yy2_a + yy2_b + YY2)
                               + (h3XY - h3XY_a);
                const float inv = __fdividef(1.f, Econv);   // E>0 => Econv>0
                accx += fabsf(fx * inv);
                accy += fabsf(fy * inv);
            }
        }

        // rotate rings
        h3E_a  = h3E_b;  h3E_b  = h3E;
        h3XX_a = h3XX_b; h3XX_b = h3XX;
        h3XY_a = h3XY_b; h3XY_b = h3XY;
        yy0_a  = yy0_b;  yy0_b  = syy;
        yy2_a  = yy2_b;  yy2_b  = YY2;
        xy0_a  = xy0_b;  xy0_b  = sxy;
        xy2_a  = xy2_b;  xy2_b  = XY2;

        cE = nE; cV = nV; cXX = nXX; cYY = nYY; cXY = nXY;
    }

    // ---- block reduction ----
    __shared__ float red[WARPS][3];
    __shared__ bool isLast;
    #pragma unroll
    for (int o = 16; o > 0; o >>= 1) {
        accx += __shfl_down_sync(0xFFFFFFFFu, accx, o);
        accy += __shfl_down_sync(0xFFFFFFFFu, accy, o);
        accE += __shfl_down_sync(0xFFFFFFFFu, accE, o);
    }
    if (lane == 0) { red[warp][0] = accx; red[warp][1] = accy; red[warp][2] = accE; }
    __syncthreads();
    if (warp == 0) {
        float ax = (lane < WARPS) ? red[lane][0] : 0.f;
        float ay = (lane < WARPS) ? red[lane][1] : 0.f;
        float aE = (lane < WARPS) ? red[lane][2] : 0.f;
        #pragma unroll
        for (int o = 4; o > 0; o >>= 1) {
            ax += __shfl_down_sync(0xFFFFFFFFu, ax, o);
            ay += __shfl_down_sync(0xFFFFFFFFu, ay, o);
            aE += __shfl_down_sync(0xFFFFFFFFu, aE, o);
        }
        if (lane == 0) {
            atomicAdd(&g_acc[0], ax);
            atomicAdd(&g_acc[1], ay);
            atomicAdd(&g_acc[2], aE);
        }
    }

    // ---- last-block finalize (single-kernel; resets state for next graph replay) ----
    if (tid == 0) {
        __threadfence();
        unsigned prev = atomicAdd(&g_count, 1u);
        isLast = (prev == NBLOCKS - 1);
    }
    __syncthreads();
    if (isLast && tid == 0) {
        const float invM = 1.0f / ((float)(WW - 2) * (float)(HH - 2));
        const float invN = 1.0f / ((float)WW * (float)HH);
        out[0] = g_acc[0] * invM + g_acc[1] * invM
               + fabsf(g_acc[2] * invN - 1.0f) * 0.01f;
        g_acc[0] = 0.f; g_acc[1] = 0.f; g_acc[2] = 0.f;
        g_count = 0u;
    }
}

extern "C" void kernel_launch(void* const* d_in, const int* in_sizes, int n_in,
                              void* d_out, int out_size) {
    const float* pred_E = (const float*)d_in[0];
    const float* pred_v = (const float*)d_in[1];
    const float* strain = (const float*)d_in[2];

    dim3 grid(GRID_X, GRID_Y);   // 9 x 64 = 576 blocks
    loss_fused_kernel<<<grid, TPB>>>(pred_E, pred_v, strain, (float*)d_out);
}